// round 7
// baseline (speedup 1.0000x reference)
#include <cuda_runtime.h>
#include <cstdint>

// compressor_17454747091102: 8-voter bitwise majority vote.
// out packed word j, bit i = 1 iff >=5 of 8 voters have bit i of word j set.
// Output dtype float32: store (float)(int32)packed_word.
//
// 256-bit access version: LDG.256 / STG.256 (.v8.b32) to halve the DRAM
// request count at constant byte traffic. Theory: the ~3.7TB/s plateau seen
// across LDG/TMA/hint variants is an outstanding-request queue limit, so
// doubling bytes/request doubles bytes in flight.

__device__ __forceinline__ void fa(uint32_t a, uint32_t b, uint32_t c,
                                   uint32_t& s, uint32_t& cy) {
    s  = a ^ b ^ c;
    cy = (a & b) | (c & (a ^ b));   // one LOP3 each
}

__device__ __forceinline__ uint32_t maj8(uint32_t w0, uint32_t w1, uint32_t w2,
                                         uint32_t w3, uint32_t w4, uint32_t w5,
                                         uint32_t w6, uint32_t w7) {
    uint32_t sa, ca, sb, cb;
    fa(w0, w1, w2, sa, ca);
    fa(w3, w4, w5, sb, cb);
    uint32_t sc = w6 ^ w7;
    uint32_t cc = w6 & w7;
    uint32_t S0, cd;
    fa(sa, sb, sc, S0, cd);
    uint32_t s1p, ce;
    fa(ca, cb, cc, s1p, ce);
    uint32_t S1 = s1p ^ cd;
    uint32_t cf = s1p & cd;
    uint32_t S2 = ce ^ cf;
    uint32_t S3 = ce & cf;
    // popcount = S0 + 2*S1 + 4*S2 + 8*S3 ; set iff >= 5
    return S3 | (S2 & (S1 | S0));
}

struct U8 { uint32_t r[8]; };

__device__ __forceinline__ U8 ldg256(const uint32_t* p) {
    U8 v;
    asm volatile("ld.global.v8.b32 {%0,%1,%2,%3,%4,%5,%6,%7}, [%8];"
                 : "=r"(v.r[0]), "=r"(v.r[1]), "=r"(v.r[2]), "=r"(v.r[3]),
                   "=r"(v.r[4]), "=r"(v.r[5]), "=r"(v.r[6]), "=r"(v.r[7])
                 : "l"(p));
    return v;
}

__device__ __forceinline__ void stg256(uint32_t* p, const uint32_t* v) {
    asm volatile("st.global.v8.b32 [%0], {%1,%2,%3,%4,%5,%6,%7,%8};"
                 :: "l"(p),
                    "r"(v[0]), "r"(v[1]), "r"(v[2]), "r"(v[3]),
                    "r"(v[4]), "r"(v[5]), "r"(v[6]), "r"(v[7])
                 : "memory");
}

__global__ void __launch_bounds__(256)
majority_vote_kernel(const uint32_t* __restrict__ src, uint32_t* __restrict__ out, int M) {
    int t = blockIdx.x * blockDim.x + threadIdx.x;
    int base = t * 8;                       // 8 consecutive words per thread
    if (base >= M) return;

    // 8 front-batched 256-bit loads (one per voter): 256B in flight per thread.
    U8 v0 = ldg256(src + 0 * (size_t)M + base);
    U8 v1 = ldg256(src + 1 * (size_t)M + base);
    U8 v2 = ldg256(src + 2 * (size_t)M + base);
    U8 v3 = ldg256(src + 3 * (size_t)M + base);
    U8 v4 = ldg256(src + 4 * (size_t)M + base);
    U8 v5 = ldg256(src + 5 * (size_t)M + base);
    U8 v6 = ldg256(src + 6 * (size_t)M + base);
    U8 v7 = ldg256(src + 7 * (size_t)M + base);

    uint32_t res[8];
    #pragma unroll
    for (int k = 0; k < 8; k++) {
        uint32_t m = maj8(v0.r[k], v1.r[k], v2.r[k], v3.r[k],
                          v4.r[k], v5.r[k], v6.r[k], v7.r[k]);
        res[k] = __float_as_uint(__int2float_rn((int)m));
    }
    stg256(out + base, res);
}

extern "C" void kernel_launch(void* const* d_in, const int* in_sizes, int n_in,
                              void* d_out, int out_size) {
    const uint32_t* src = (const uint32_t*)d_in[1];
    long long n_src = in_sizes[1];
    if (n_in > 1 && in_sizes[0] > in_sizes[1]) { src = (const uint32_t*)d_in[0]; n_src = in_sizes[0]; }

    int M = (int)(n_src / 8);           // packed words per voter == out_size

    int threads = 256;
    int total_threads = M / 8;          // 131072
    int blocks = (total_threads + threads - 1) / threads;   // 512
    majority_vote_kernel<<<blocks, threads>>>(src, (uint32_t*)d_out, M);
}

// round 9
// speedup vs baseline: 1.0510x; 1.0510x over previous
#include <cuda_runtime.h>
#include <cstdint>

// compressor_17454747091102: 8-voter bitwise majority vote.
// out packed word j, bit i = 1 iff >=5 of 8 voters have bit i of word j set.
// Output dtype float32: store (float)(int32)packed_word.
//
// Full-occupancy variant: 2 words/thread (uint2), ~28 regs -> 8 blocks/SM,
// 100% occupancy, 16K warps chip-wide. Theory: the ~3.7TB/s cold plateau is
// arbiter-stream-count limited; double the concurrent warp streams.

__device__ __forceinline__ void fa(uint32_t a, uint32_t b, uint32_t c,
                                   uint32_t& s, uint32_t& cy) {
    s  = a ^ b ^ c;
    cy = (a & b) | (c & (a ^ b));   // one LOP3 each
}

__device__ __forceinline__ uint32_t maj8(uint32_t w0, uint32_t w1, uint32_t w2,
                                         uint32_t w3, uint32_t w4, uint32_t w5,
                                         uint32_t w6, uint32_t w7) {
    uint32_t sa, ca, sb, cb;
    fa(w0, w1, w2, sa, ca);
    fa(w3, w4, w5, sb, cb);
    uint32_t sc = w6 ^ w7;
    uint32_t cc = w6 & w7;
    uint32_t S0, cd;
    fa(sa, sb, sc, S0, cd);
    uint32_t s1p, ce;
    fa(ca, cb, cc, s1p, ce);
    uint32_t S1 = s1p ^ cd;
    uint32_t cf = s1p & cd;
    uint32_t S2 = ce ^ cf;
    uint32_t S3 = ce & cf;
    // popcount = S0 + 2*S1 + 4*S2 + 8*S3 ; set iff >= 5
    return S3 | (S2 & (S1 | S0));
}

__global__ void __launch_bounds__(256, 8)
majority_vote_kernel(const uint2* __restrict__ src, float2* __restrict__ out, int m2) {
    int idx = blockIdx.x * blockDim.x + threadIdx.x;
    if (idx >= m2) return;

    // 8 front-batched independent 64-bit loads, one per voter.
    uint2 v0 = src[0 * (size_t)m2 + idx];
    uint2 v1 = src[1 * (size_t)m2 + idx];
    uint2 v2 = src[2 * (size_t)m2 + idx];
    uint2 v3 = src[3 * (size_t)m2 + idx];
    uint2 v4 = src[4 * (size_t)m2 + idx];
    uint2 v5 = src[5 * (size_t)m2 + idx];
    uint2 v6 = src[6 * (size_t)m2 + idx];
    uint2 v7 = src[7 * (size_t)m2 + idx];

    float2 r;
    r.x = __int2float_rn((int)maj8(v0.x, v1.x, v2.x, v3.x, v4.x, v5.x, v6.x, v7.x));
    r.y = __int2float_rn((int)maj8(v0.y, v1.y, v2.y, v3.y, v4.y, v5.y, v6.y, v7.y));
    out[idx] = r;
}

extern "C" void kernel_launch(void* const* d_in, const int* in_sizes, int n_in,
                              void* d_out, int out_size) {
    const uint32_t* src = (const uint32_t*)d_in[1];
    long long n_src = in_sizes[1];
    if (n_in > 1 && in_sizes[0] > in_sizes[1]) { src = (const uint32_t*)d_in[0]; n_src = in_sizes[0]; }

    int M  = (int)(n_src / 8);     // packed words per voter == out_size
    int m2 = M / 2;                // uint2 chunks (524288)

    int threads = 256;
    int blocks  = (m2 + threads - 1) / threads;   // 2048
    majority_vote_kernel<<<blocks, threads>>>((const uint2*)src, (float2*)d_out, m2);
}